// round 13
// baseline (speedup 1.0000x reference)
#include <cuda_runtime.h>
#include <cuda_fp16.h>
#include <math.h>
#include <stdint.h>

// ================= Problem constants =================
#define BATCH   16384
#define NFIELD  10
#define EMB     32
#define DENSE   16
#define K0      336         // 21 * 16
#define N0      256
#define N1      128
#define N2      64
#define MTILE   64
#define NCTA    (BATCH / MTILE)   // 256
#define NTHR    256
#define GK_L1   21
#define GK_L2   37
#define GK_END  45

__constant__ int c_offsets[NFIELD] = {
    0, 1000000, 1100000, 1101008, 1102012,
    1102114, 1103114, 1103614, 1103664, 1103776
};

// ================= Device scratch: weight stage images (fp16) =====
__device__ __align__(128) char g_S0[21 * 12288];
__device__ __align__(128) char g_S1[16 * 6144];
__device__ __align__(128) char g_S2[8 * 3072];
__device__ float g_bf0[N0], g_bf1[N1], g_bf2[N2];

// ================= PTX helpers =================
__device__ __forceinline__ uint32_t smem_u32(const void* p) {
    uint32_t a;
    asm("{ .reg .u64 t; cvta.to.shared.u64 t, %1; cvt.u32.u64 %0, t; }" : "=r"(a) : "l"(p));
    return a;
}
__device__ __forceinline__ void ldsm4(uint32_t* r, uint32_t a) {
    asm volatile("ldmatrix.sync.aligned.m8n8.x4.shared.b16 {%0,%1,%2,%3}, [%4];"
        : "=r"(r[0]), "=r"(r[1]), "=r"(r[2]), "=r"(r[3]) : "r"(a));
}
__device__ __forceinline__ void mma_f16(float* c, const uint32_t* a, const uint32_t* b) {
    asm volatile("mma.sync.aligned.m16n8k16.row.col.f32.f16.f16.f32 "
        "{%0,%1,%2,%3}, {%4,%5,%6,%7}, {%8,%9}, {%0,%1,%2,%3};"
        : "+f"(c[0]), "+f"(c[1]), "+f"(c[2]), "+f"(c[3])
        : "r"(a[0]), "r"(a[1]), "r"(a[2]), "r"(a[3]), "r"(b[0]), "r"(b[1]));
}
__device__ __forceinline__ uint32_t pack_h2(__half a, __half b) {
    __half2 t = __halves2half2(a, b);
    return *(uint32_t*)&t;
}

#define MBAR_INIT(a, c) \
    asm volatile("mbarrier.init.shared.b64 [%0], %1;" :: "r"(a), "r"((uint32_t)(c)) : "memory")
__device__ __forceinline__ void mbar_arrive(uint32_t a) {
    asm volatile("{ .reg .b64 _t; mbarrier.arrive.shared.b64 _t, [%0]; }" :: "r"(a) : "memory");
}
__device__ __forceinline__ void mbar_expect_tx(uint32_t a, uint32_t bytes) {
    asm volatile("mbarrier.arrive.expect_tx.shared.b64 _, [%0], %1;"
        :: "r"(a), "r"(bytes) : "memory");
}
__device__ __forceinline__ void bulk_g2s(uint32_t dst, const void* src, uint32_t bytes,
                                         uint32_t mbar) {
    asm volatile("cp.async.bulk.shared::cluster.global.mbarrier::complete_tx::bytes "
        "[%0], [%1], %2, [%3];"
        :: "r"(dst), "l"(src), "r"(bytes), "r"(mbar) : "memory");
}
#define FENCE_PROXY_ASYNC() asm volatile("fence.proxy.async.shared::cta;" ::: "memory")
#define MBAR_WAIT(mbar, par) do { \
    uint32_t _m = (uint32_t)(mbar); uint32_t _p = (uint32_t)(par); uint32_t _d; \
    asm volatile("{\n\t.reg .pred p;\n\t" \
        "mbarrier.try_wait.parity.acquire.cta.shared::cta.b64 p, [%1], %2;\n\t" \
        "selp.b32 %0, 1, 0, p;\n\t}" : "=r"(_d) : "r"(_m), "r"(_p) : "memory"); \
    if (!_d) { \
        asm volatile("{\n\t.reg .pred P1;\n\t" \
            "WL_%=:\n\t" \
            "mbarrier.try_wait.parity.acquire.cta.shared::cta.b64 P1, [%0], %1, 0x989680;\n\t" \
            "@P1 bra.uni WD_%=;\n\t" \
            "bra.uni WL_%=;\n\t" \
            "WD_%=:\n\t}" :: "r"(_m), "r"(_p) : "memory"); \
    } \
} while (0)

// ================= Kernel 1: weight prep -> fp16 staged blobs =================
#define S0SZ (N0 * K0)
#define S1SZ (N1 * N0)
#define S2SZ (N2 * N1)
#define PREP_TOT (S0SZ + S1SZ + S2SZ)

__global__ void prep_all(const float* __restrict__ W0, const float* __restrict__ b0,
                         const float* __restrict__ g0, const float* __restrict__ be0,
                         const float* __restrict__ W1, const float* __restrict__ b1,
                         const float* __restrict__ g1, const float* __restrict__ be1,
                         const float* __restrict__ W2, const float* __restrict__ b2,
                         const float* __restrict__ g2, const float* __restrict__ be2)
{
    const float inv = 0.9999950000374997f;   // 1/sqrt(1+1e-5)
    int i = blockIdx.x * blockDim.x + threadIdx.x;
    if (i >= PREP_TOT) return;
    char* base; uint32_t stagesz; const float *W, *g; int n, k, li;
    if (i < S0SZ) {
        li = i; n = li / K0; k = li - n * K0;
        W = W0; g = g0; base = g_S0; stagesz = 12288;
        if (li < N0) g_bf0[li] = b0[li] * (g0[li] * inv) + be0[li];
    } else if (i < S0SZ + S1SZ) {
        li = i - S0SZ; n = li >> 8; k = li & 255;
        W = W1; g = g1; base = g_S1; stagesz = 6144;
        if (li < N1) g_bf1[li] = b1[li] * (g1[li] * inv) + be1[li];
    } else {
        li = i - S0SZ - S1SZ; n = li >> 7; k = li & 127;
        W = W2; g = g2; base = g_S2; stagesz = 3072;
        if (li < N2) g_bf2[li] = b2[li] * (g2[li] * inv) + be2[li];
    }
    float w = W[li] * (g[n] * inv);
    int ks = k >> 4, kk = k & 15;
    uint32_t off = (uint32_t)ks * stagesz + (uint32_t)n * 48u
                 + (uint32_t)((kk >> 3) << 4) + (uint32_t)((kk & 7) << 1);
    *(__half*)(base + off) = __float2half_rn(w);
}

// ================= Kernel 2: fused embed + FM + HMMA MLP (fp16, 64 rows) ====
// SMEM map (per CTA, ~81.2 KB -> 2 CTAs/SM):
//   X    @ 0     : [64][688B] = 44032   (dead after layer0: C1 @0: 64x528=33792;
//   WSTG @ 44032 : 3 x 12288 = 36864     then C2 @0: 64x272=17408, C3F @17408)
//   FMS  @ 80896 : 256
//   BARS @ 81152 : full x3 (24B), empty x3 (24B)
#define X_OFF  0
#define XSTR   688
#define WSTG   44032
#define WSSZ   12288
#define C1_OFF 0
#define C2_OFF 0
#define C3F    17408
#define FMS    80896
#define BARS   81152
#define SMEM_DYN (81152 + 64)

__global__ __launch_bounds__(NTHR, 2)
void mlp_kernel(const int* __restrict__ sp, const float* __restrict__ dense,
                const float* __restrict__ emb, const float* __restrict__ bias,
                const float* __restrict__ fmb,
                const float* __restrict__ Wo, const float* __restrict__ bo,
                float* __restrict__ out)
{
    extern __shared__ char smc[];
    const uint32_t sb = smem_u32(smc);
    const int t = threadIdx.x, w = t >> 5, lane = t & 31;
    const int m0g = blockIdx.x * MTILE;
    const int wm = (w >> 2) * 32;       // 0 or 32
    const int wn = (w & 3);
    const uint32_t lrow = (uint32_t)(lane & 15);
    const uint32_t lhalf = (uint32_t)(lane >> 4) * 16u;
    const uint32_t fullb = sb + BARS;
    const uint32_t emptyb = sb + BARS + 24;

    // 3-stage producer: one bulk copy per stage (single thread)
    auto produce = [&](int gkp) {
        if (t != 0) return;
        int slot = gkp % 3;
        uint32_t stg = sb + WSTG + (uint32_t)slot * WSSZ;
        if (gkp >= 3) MBAR_WAIT(emptyb + slot * 8, ((gkp / 3) - 1) & 1);
        const char* src; uint32_t bytes;
        if (gkp < GK_L1)      { src = g_S0 + (size_t)gkp * 12288;            bytes = 12288; }
        else if (gkp < GK_L2) { src = g_S1 + (size_t)(gkp - GK_L1) * 6144;   bytes = 6144; }
        else                  { src = g_S2 + (size_t)(gkp - GK_L2) * 3072;   bytes = 3072; }
        mbar_expect_tx(fullb + slot * 8, bytes);
        bulk_g2s(stg, src, bytes, fullb + slot * 8);
    };

    // ---------------- Init barriers, kick stages 0..2, gather X, FM ----------------
    if (t == 0) {
        MBAR_INIT(fullb, 1);  MBAR_INIT(fullb + 8, 1);  MBAR_INIT(fullb + 16, 1);
        MBAR_INIT(emptyb, 8); MBAR_INIT(emptyb + 8, 8); MBAR_INIT(emptyb + 16, 8);
        FENCE_PROXY_ASYNC();
    }
    __syncthreads();
    produce(0);
    produce(1);
    produce(2);

    // gather: 8 warps x 8 samples = 64
#pragma unroll
    for (int i = 0; i < 8; i++) {
        int m = w * 8 + i;
        int b = m0g + m;
        float e[NFIELD];
#pragma unroll
        for (int f = 0; f < NFIELD; f++) {
            int row = sp[b * NFIELD + f] + c_offsets[f];
            e[f] = __ldg(&emb[(size_t)row * EMB + lane]);
        }
        float s = 0.f, sq = 0.f;
#pragma unroll
        for (int f = 0; f < NFIELD; f++) {
            s += e[f]; sq += e[f] * e[f];
            *(__half*)(smc + X_OFF + m * XSTR + (f * EMB + lane) * 2) = __float2half_rn(e[f]);
        }
        if (lane < DENSE)
            *(__half*)(smc + X_OFF + m * XSTR + (320 + lane) * 2) =
                __float2half_rn(dense[b * DENSE + lane]);
        float part = 0.5f * (s * s - sq);
        if (lane < NFIELD)
            part += __ldg(&bias[sp[b * NFIELD + lane] + c_offsets[lane]]);
#pragma unroll
        for (int d = 16; d > 0; d >>= 1)
            part += __shfl_down_sync(0xFFFFFFFFu, part, d);
        if (lane == 0) *(float*)(smc + FMS + m * 4) = part;
    }
    __syncthreads();   // X visible

    // ================= Layer 0: [64x336] -> 256 =================
    float acc0[2][8][4];
#pragma unroll
    for (int i = 0; i < 2; i++)
#pragma unroll
        for (int j = 0; j < 8; j++)
#pragma unroll
            for (int q = 0; q < 4; q++) acc0[i][j][q] = 0.f;

    uint32_t aH[2][4];
#pragma unroll
    for (int i = 0; i < 2; i++)
        ldsm4(aH[i], sb + X_OFF + (wm + 16 * i + lrow) * XSTR + lhalf);

    for (int ks = 0; ks < 21; ks++) {
        const int gks = ks, slot = gks % 3, par = (gks / 3) & 1;
        MBAR_WAIT(fullb + slot * 8, par);
        uint32_t stg = sb + WSTG + (uint32_t)slot * WSSZ;
        uint32_t bH[8][2];
#pragma unroll
        for (int nb = 0; nb < 4; nb++) {
            uint32_t rh[4];
            ldsm4(rh, stg + (wn * 64 + 16 * nb + lrow) * 48 + lhalf);
            bH[2 * nb][0] = rh[0]; bH[2 * nb][1] = rh[2];
            bH[2 * nb + 1][0] = rh[1]; bH[2 * nb + 1][1] = rh[3];
        }
        if (lane == 0) mbar_arrive(emptyb + slot * 8);
#pragma unroll
        for (int j = 0; j < 8; j++)
            mma_f16(acc0[0][j], aH[0], bH[j]);
        uint32_t aN[2][4];
        if (ks + 1 < 21) {
#pragma unroll
            for (int i = 0; i < 2; i++)
                ldsm4(aN[i], sb + X_OFF + (wm + 16 * i + lrow) * XSTR + (ks + 1) * 32 + lhalf);
        }
#pragma unroll
        for (int j = 0; j < 8; j++)
            mma_f16(acc0[1][j], aH[1], bH[j]);
        if (ks + 1 < 21) {
#pragma unroll
            for (int i = 0; i < 2; i++)
#pragma unroll
                for (int q = 0; q < 4; q++) aH[i][q] = aN[i][q];
        }
        produce(gks + 3);
    }
    __syncthreads();    // X reads done; region dead

    // epilogue 0 -> C1 (aliases X)
    {
#pragma unroll
        for (int i = 0; i < 2; i++)
#pragma unroll
            for (int j = 0; j < 8; j++) {
                int col = wn * 64 + j * 8 + (lane & 3) * 2;
                int row = wm + 16 * i + (lane >> 2);
                float b0v = g_bf0[col], b1v = g_bf0[col + 1];
                *(uint32_t*)(smc + C1_OFF + row * 528 + col * 2) =
                    pack_h2(__float2half_rn(fmaxf(acc0[i][j][0] + b0v, 0.f)),
                            __float2half_rn(fmaxf(acc0[i][j][1] + b1v, 0.f)));
                *(uint32_t*)(smc + C1_OFF + (row + 8) * 528 + col * 2) =
                    pack_h2(__float2half_rn(fmaxf(acc0[i][j][2] + b0v, 0.f)),
                            __float2half_rn(fmaxf(acc0[i][j][3] + b1v, 0.f)));
            }
    }
    __syncthreads();    // C1 visible

    // ================= Layer 1: [64x256] -> 128 =================
    float acc1[2][4][4];
#pragma unroll
    for (int i = 0; i < 2; i++)
#pragma unroll
        for (int j = 0; j < 4; j++)
#pragma unroll
            for (int q = 0; q < 4; q++) acc1[i][j][q] = 0.f;

#pragma unroll
    for (int i = 0; i < 2; i++)
        ldsm4(aH[i], sb + C1_OFF + (wm + 16 * i + lrow) * 528 + lhalf);

    for (int ks = 0; ks < 16; ks++) {
        const int gks = GK_L1 + ks, slot = gks % 3, par = (gks / 3) & 1;
        MBAR_WAIT(fullb + slot * 8, par);
        uint32_t stg = sb + WSTG + (uint32_t)slot * WSSZ;
        uint32_t bH[4][2];
#pragma unroll
        for (int nb = 0; nb < 2; nb++) {
            uint32_t rh[4];
            ldsm4(rh, stg + (wn * 32 + 16 * nb + lrow) * 48 + lhalf);
            bH[2 * nb][0] = rh[0]; bH[2 * nb][1] = rh[2];
            bH[2 * nb + 1][0] = rh[1]; bH[2 * nb + 1][1] = rh[3];
        }
        if (lane == 0) mbar_arrive(emptyb + slot * 8);
#pragma unroll
        for (int j = 0; j < 4; j++)
            mma_f16(acc1[0][j], aH[0], bH[j]);
        uint32_t aN[2][4];
        if (ks + 1 < 16) {
#pragma unroll
            for (int i = 0; i < 2; i++)
                ldsm4(aN[i], sb + C1_OFF + (wm + 16 * i + lrow) * 528 + (ks + 1) * 32 + lhalf);
        }
#pragma unroll
        for (int j = 0; j < 4; j++)
            mma_f16(acc1[1][j], aH[1], bH[j]);
        if (ks + 1 < 16) {
#pragma unroll
            for (int i = 0; i < 2; i++)
#pragma unroll
                for (int q = 0; q < 4; q++) aH[i][q] = aN[i][q];
        }
        produce(gks + 3);
    }
    __syncthreads();    // C1 reads done; region dead

    // epilogue 1 -> C2 (aliases C1)
    {
#pragma unroll
        for (int i = 0; i < 2; i++)
#pragma unroll
            for (int j = 0; j < 4; j++) {
                int col = wn * 32 + j * 8 + (lane & 3) * 2;
                int row = wm + 16 * i + (lane >> 2);
                float b0v = g_bf1[col], b1v = g_bf1[col + 1];
                *(uint32_t*)(smc + C2_OFF + row * 272 + col * 2) =
                    pack_h2(__float2half_rn(fmaxf(acc1[i][j][0] + b0v, 0.f)),
                            __float2half_rn(fmaxf(acc1[i][j][1] + b1v, 0.f)));
                *(uint32_t*)(smc + C2_OFF + (row + 8) * 272 + col * 2) =
                    pack_h2(__float2half_rn(fmaxf(acc1[i][j][2] + b0v, 0.f)),
                            __float2half_rn(fmaxf(acc1[i][j][3] + b1v, 0.f)));
            }
    }
    __syncthreads();    // C2 visible

    // ================= Layer 2: [64x128] -> 64 =================
    float acc2[2][2][4];
#pragma unroll
    for (int i = 0; i < 2; i++)
#pragma unroll
        for (int j = 0; j < 2; j++)
#pragma unroll
            for (int q = 0; q < 4; q++) acc2[i][j][q] = 0.f;

#pragma unroll
    for (int i = 0; i < 2; i++)
        ldsm4(aH[i], sb + C2_OFF + (wm + 16 * i + lrow) * 272 + lhalf);

    for (int ks = 0; ks < 8; ks++) {
        const int gks = GK_L2 + ks, slot = gks % 3, par = (gks / 3) & 1;
        MBAR_WAIT(fullb + slot * 8, par);
        uint32_t stg = sb + WSTG + (uint32_t)slot * WSSZ;
        uint32_t bH[2][2];
        {
            uint32_t rh[4];
            ldsm4(rh, stg + (wn * 16 + lrow) * 48 + lhalf);
            bH[0][0] = rh[0]; bH[0][1] = rh[2]; bH[1][0] = rh[1]; bH[1][1] = rh[3];
        }
        if (lane == 0) mbar_arrive(emptyb + slot * 8);
#pragma unroll
        for (int j = 0; j < 2; j++)
            mma_f16(acc2[0][j], aH[0], bH[j]);
        uint32_t aN[2][4];
        if (ks + 1 < 8) {
#pragma unroll
            for (int i = 0; i < 2; i++)
                ldsm4(aN[i], sb + C2_OFF + (wm + 16 * i + lrow) * 272 + (ks + 1) * 32 + lhalf);
        }
#pragma unroll
        for (int j = 0; j < 2; j++)
            mma_f16(acc2[1][j], aH[1], bH[j]);
        if (ks + 1 < 8) {
#pragma unroll
            for (int i = 0; i < 2; i++)
#pragma unroll
                for (int q = 0; q < 4; q++) aH[i][q] = aN[i][q];
        }
        if (gks + 3 < GK_END) produce(gks + 3);
    }

    // epilogue 2 -> C3 (f32, above C2 region)
    {
#pragma unroll
        for (int i = 0; i < 2; i++)
#pragma unroll
            for (int j = 0; j < 2; j++) {
                int col = wn * 16 + j * 8 + (lane & 3) * 2;
                int row = wm + 16 * i + (lane >> 2);
                float b0v = g_bf2[col], b1v = g_bf2[col + 1];
                float2 v01 = make_float2(fmaxf(acc2[i][j][0] + b0v, 0.f),
                                         fmaxf(acc2[i][j][1] + b1v, 0.f));
                float2 v23 = make_float2(fmaxf(acc2[i][j][2] + b0v, 0.f),
                                         fmaxf(acc2[i][j][3] + b1v, 0.f));
                *(float2*)(smc + C3F + row * 272 + col * 4) = v01;
                *(float2*)(smc + C3F + (row + 8) * 272 + col * 4) = v23;
            }
    }
    __syncthreads();

    // ================= Output: dot Wo + fm + sigmoid =================
    if (t < MTILE) {
        const float* c3 = (const float*)(smc + C3F) + t * 68;
        float s = *(const float*)(smc + FMS + t * 4) + fmb[0] + bo[0];
#pragma unroll
        for (int k = 0; k < N2; k++)
            s = fmaf(c3[k], __ldg(&Wo[k]), s);
        out[m0g + t] = 1.f / (1.f + __expf(-s));
    }
}

// ================= Launch =================
extern "C" void kernel_launch(void* const* d_in, const int* in_sizes, int n_in,
                              void* d_out, int out_size)
{
    const int*   sp    = (const int*)  d_in[0];
    const float* dense = (const float*)d_in[1];
    const float* emb   = (const float*)d_in[2];
    const float* bias  = (const float*)d_in[3];
    const float* fmb   = (const float*)d_in[4];
    const float* Wo    = (const float*)d_in[5];
    const float* bo    = (const float*)d_in[6];
    const float* W0    = (const float*)d_in[7];
    const float* b0    = (const float*)d_in[8];
    const float* g0    = (const float*)d_in[9];
    const float* be0   = (const float*)d_in[10];
    const float* W1    = (const float*)d_in[11];
    const float* b1    = (const float*)d_in[12];
    const float* g1    = (const float*)d_in[13];
    const float* be1   = (const float*)d_in[14];
    const float* W2    = (const float*)d_in[15];
    const float* b2    = (const float*)d_in[16];
    const float* g2    = (const float*)d_in[17];
    const float* be2   = (const float*)d_in[18];
    float* out = (float*)d_out;

    prep_all<<<(PREP_TOT + 255) / 256, 256>>>(W0, b0, g0, be0, W1, b1, g1, be1, W2, b2, g2, be2);

    cudaFuncSetAttribute(mlp_kernel, cudaFuncAttributeMaxDynamicSharedMemorySize, SMEM_DYN);
    mlp_kernel<<<NCTA, NTHR, SMEM_DYN>>>(sp, dense, emb, bias, fmb, Wo, bo, out);
}

// round 14
// speedup vs baseline: 1.1633x; 1.1633x over previous
#include <cuda_runtime.h>
#include <cuda_fp16.h>
#include <math.h>
#include <stdint.h>

// ================= Problem constants =================
#define BATCH   16384
#define NFIELD  10
#define EMB     32
#define DENSE   16
#define K0      336
#define K0P     352          // padded to 22 k-steps
#define N0      256
#define N1      128
#define N2      64
#define MTILE   64
#define NCTA    (BATCH / MTILE)   // 256
#define NTHR    256
// chunk schedule: L0 = 11 chunks (22 ksteps), L1 = 8, L2 = 4
#define GC_L1   11
#define GC_L2   19
#define GC_END  23

__constant__ int c_offsets[NFIELD] = {
    0, 1000000, 1100000, 1101008, 1102012,
    1102114, 1103114, 1103614, 1103664, 1103776
};

// ================= Device scratch: weight k-step images (fp16) =====
__device__ __align__(128) char g_S0[22 * 12288];   // 22 ksteps (incl. zero pad)
__device__ __align__(128) char g_S1[16 * 6144];
__device__ __align__(128) char g_S2[8 * 3072];
__device__ float g_bf0[N0], g_bf1[N1], g_bf2[N2];

// ================= PTX helpers =================
__device__ __forceinline__ uint32_t smem_u32(const void* p) {
    uint32_t a;
    asm("{ .reg .u64 t; cvta.to.shared.u64 t, %1; cvt.u32.u64 %0, t; }" : "=r"(a) : "l"(p));
    return a;
}
__device__ __forceinline__ void ldsm4(uint32_t* r, uint32_t a) {
    asm volatile("ldmatrix.sync.aligned.m8n8.x4.shared.b16 {%0,%1,%2,%3}, [%4];"
        : "=r"(r[0]), "=r"(r[1]), "=r"(r[2]), "=r"(r[3]) : "r"(a));
}
__device__ __forceinline__ void mma_f16(float* c, const uint32_t* a, const uint32_t* b) {
    asm volatile("mma.sync.aligned.m16n8k16.row.col.f32.f16.f16.f32 "
        "{%0,%1,%2,%3}, {%4,%5,%6,%7}, {%8,%9}, {%0,%1,%2,%3};"
        : "+f"(c[0]), "+f"(c[1]), "+f"(c[2]), "+f"(c[3])
        : "r"(a[0]), "r"(a[1]), "r"(a[2]), "r"(a[3]), "r"(b[0]), "r"(b[1]));
}
__device__ __forceinline__ uint32_t pack_h2(__half a, __half b) {
    __half2 t = __halves2half2(a, b);
    return *(uint32_t*)&t;
}

#define MBAR_INIT(a, c) \
    asm volatile("mbarrier.init.shared.b64 [%0], %1;" :: "r"(a), "r"((uint32_t)(c)) : "memory")
__device__ __forceinline__ void mbar_arrive(uint32_t a) {
    asm volatile("{ .reg .b64 _t; mbarrier.arrive.shared.b64 _t, [%0]; }" :: "r"(a) : "memory");
}
__device__ __forceinline__ void mbar_expect_tx(uint32_t a, uint32_t bytes) {
    asm volatile("mbarrier.arrive.expect_tx.shared.b64 _, [%0], %1;"
        :: "r"(a), "r"(bytes) : "memory");
}
__device__ __forceinline__ void bulk_g2s(uint32_t dst, const void* src, uint32_t bytes,
                                         uint32_t mbar) {
    asm volatile("cp.async.bulk.shared::cluster.global.mbarrier::complete_tx::bytes "
        "[%0], [%1], %2, [%3];"
        :: "r"(dst), "l"(src), "r"(bytes), "r"(mbar) : "memory");
}
#define FENCE_PROXY_ASYNC() asm volatile("fence.proxy.async.shared::cta;" ::: "memory")
#define MBAR_WAIT(mbar, par) do { \
    uint32_t _m = (uint32_t)(mbar); uint32_t _p = (uint32_t)(par); uint32_t _d; \
    asm volatile("{\n\t.reg .pred p;\n\t" \
        "mbarrier.try_wait.parity.acquire.cta.shared::cta.b64 p, [%1], %2;\n\t" \
        "selp.b32 %0, 1, 0, p;\n\t}" : "=r"(_d) : "r"(_m), "r"(_p) : "memory"); \
    if (!_d) { \
        asm volatile("{\n\t.reg .pred P1;\n\t" \
            "WL_%=:\n\t" \
            "mbarrier.try_wait.parity.acquire.cta.shared::cta.b64 P1, [%0], %1, 0x989680;\n\t" \
            "@P1 bra.uni WD_%=;\n\t" \
            "bra.uni WL_%=;\n\t" \
            "WD_%=:\n\t}" :: "r"(_m), "r"(_p) : "memory"); \
    } \
} while (0)

// ================= Kernel 1: weight prep -> fp16 staged blobs =================
#define S0P  (N0 * K0P)       // 90112 (incl. zero pad cols)
#define S1SZ (N1 * N0)        // 32768
#define S2SZ (N2 * N1)        // 8192
#define PREP_TOT (S0P + S1SZ + S2SZ)   // 131072

__global__ void prep_all(const float* __restrict__ W0, const float* __restrict__ b0,
                         const float* __restrict__ g0, const float* __restrict__ be0,
                         const float* __restrict__ W1, const float* __restrict__ b1,
                         const float* __restrict__ g1, const float* __restrict__ be1,
                         const float* __restrict__ W2, const float* __restrict__ b2,
                         const float* __restrict__ g2, const float* __restrict__ be2)
{
    const float inv = 0.9999950000374997f;   // 1/sqrt(1+1e-5)
    int i = blockIdx.x * blockDim.x + threadIdx.x;
    if (i >= PREP_TOT) return;
    char* base; uint32_t kimg; float w; int n, k;
    if (i < S0P) {
        n = i / K0P; k = i - n * K0P;
        base = g_S0; kimg = 12288;
        w = (k < K0) ? W0[n * K0 + k] * (g0[n] * inv) : 0.f;
        if (i < N0) g_bf0[i] = b0[i] * (g0[i] * inv) + be0[i];
    } else if (i < S0P + S1SZ) {
        int li = i - S0P; n = li >> 8; k = li & 255;
        base = g_S1; kimg = 6144;
        w = W1[li] * (g1[n] * inv);
        if (li < N1) g_bf1[li] = b1[li] * (g1[li] * inv) + be1[li];
    } else {
        int li = i - S0P - S1SZ; n = li >> 7; k = li & 127;
        base = g_S2; kimg = 3072;
        w = W2[li] * (g2[n] * inv);
        if (li < N2) g_bf2[li] = b2[li] * (g2[li] * inv) + be2[li];
    }
    int ks = k >> 4, kk = k & 15;
    uint32_t off = (uint32_t)ks * kimg + (uint32_t)n * 48u
                 + (uint32_t)((kk >> 3) << 4) + (uint32_t)((kk & 7) << 1);
    *(__half*)(base + off) = __float2half_rn(w);
}

// ================= Kernel 2: fused embed + FM + HMMA MLP =================
// SMEM map (~95.6 KB -> 2 CTAs/SM):
//   X    @ 0     : [64][720B] = 46080   (dead after L0: C1 @0 = 64x528 = 33792;
//   WSTG @ 46080 : 2 x 24576  = 49152    then C2 @0 = 17408, C3F @17408)
//   FMS  @ 95232 : 256
//   BARS @ 95488
#define X_OFF  0
#define XSTR   720
#define WSTG   46080
#define WSSZ   24576
#define C1_OFF 0
#define C2_OFF 0
#define C3F    17408
#define FMS    95232
#define BARS   95488
#define SMEM_DYN (95488 + 64)

__global__ __launch_bounds__(NTHR, 2)
void mlp_kernel(const int* __restrict__ sp, const float* __restrict__ dense,
                const float* __restrict__ emb, const float* __restrict__ bias,
                const float* __restrict__ fmb,
                const float* __restrict__ Wo, const float* __restrict__ bo,
                float* __restrict__ out)
{
    extern __shared__ char smc[];
    const uint32_t sb = smem_u32(smc);
    const int t = threadIdx.x, w = t >> 5, lane = t & 31;
    const int m0g = blockIdx.x * MTILE;
    const int wm = (w >> 2) * 32;
    const int wn = (w & 3);
    const uint32_t lrow = (uint32_t)(lane & 15);
    const uint32_t lhalf = (uint32_t)(lane >> 4) * 16u;
    const uint32_t fullb = sb + BARS;
    const uint32_t emptyb = sb + BARS + 16;

    // 2-stage, 2-kstep-chunk producer (single thread)
    auto produce = [&](int cg) {
        if (t != 0) return;
        int slot = cg & 1;
        uint32_t stg = sb + WSTG + (uint32_t)slot * WSSZ;
        if (cg >= 2) MBAR_WAIT(emptyb + slot * 8, ((cg - 2) >> 1) & 1);
        const char* src; uint32_t bytes;
        if (cg < GC_L1)      { src = g_S0 + (size_t)cg * 24576;            bytes = 24576; }
        else if (cg < GC_L2) { src = g_S1 + (size_t)(cg - GC_L1) * 12288;  bytes = 12288; }
        else                 { src = g_S2 + (size_t)(cg - GC_L2) * 6144;   bytes = 6144; }
        mbar_expect_tx(fullb + slot * 8, bytes);
        bulk_g2s(stg, src, bytes, fullb + slot * 8);
    };

    // ---------------- Init, kick chunks 0/1, gather X (+zero pad), FM ----------------
    if (t == 0) {
        MBAR_INIT(fullb, 1);   MBAR_INIT(fullb + 8, 1);
        MBAR_INIT(emptyb, 8);  MBAR_INIT(emptyb + 8, 8);
        FENCE_PROXY_ASYNC();
    }
    __syncthreads();
    produce(0);
    produce(1);

#pragma unroll
    for (int i = 0; i < 8; i++) {
        int m = w * 8 + i;
        int b = m0g + m;
        float e[NFIELD];
#pragma unroll
        for (int f = 0; f < NFIELD; f++) {
            int row = sp[b * NFIELD + f] + c_offsets[f];
            e[f] = __ldg(&emb[(size_t)row * EMB + lane]);
        }
        float s = 0.f, sq = 0.f;
#pragma unroll
        for (int f = 0; f < NFIELD; f++) {
            s += e[f]; sq += e[f] * e[f];
            *(__half*)(smc + X_OFF + m * XSTR + (f * EMB + lane) * 2) = __float2half_rn(e[f]);
        }
        if (lane < DENSE)
            *(__half*)(smc + X_OFF + m * XSTR + (320 + lane) * 2) =
                __float2half_rn(dense[b * DENSE + lane]);
        if (lane < 16)   // zero pad cols 336..351
            *(__half*)(smc + X_OFF + m * XSTR + (336 + lane) * 2) = __float2half_rn(0.f);
        float part = 0.5f * (s * s - sq);
        if (lane < NFIELD)
            part += __ldg(&bias[sp[b * NFIELD + lane] + c_offsets[lane]]);
#pragma unroll
        for (int d = 16; d > 0; d >>= 1)
            part += __shfl_down_sync(0xFFFFFFFFu, part, d);
        if (lane == 0) *(float*)(smc + FMS + m * 4) = part;
    }
    __syncthreads();   // X visible

    // ================= Layer 0: [64x352] -> 256, 11 chunks =================
    float acc0[2][8][4];
#pragma unroll
    for (int i = 0; i < 2; i++)
#pragma unroll
        for (int j = 0; j < 8; j++)
#pragma unroll
            for (int q = 0; q < 4; q++) acc0[i][j][q] = 0.f;

    uint32_t a0[2][4], a1[2][4];
#pragma unroll
    for (int i = 0; i < 2; i++)
        ldsm4(a0[i], sb + X_OFF + (wm + 16 * i + lrow) * XSTR + lhalf);

    for (int c = 0; c < 11; c++) {
        const int slot = c & 1, par = (c >> 1) & 1;
        // A for kstep 2c+1 (always-readable smem)
#pragma unroll
        for (int i = 0; i < 2; i++)
            ldsm4(a1[i], sb + X_OFF + (wm + 16 * i + lrow) * XSTR + (2 * c + 1) * 32 + lhalf);
        MBAR_WAIT(fullb + slot * 8, par);
        uint32_t stg = sb + WSTG + (uint32_t)slot * WSSZ;
        uint32_t bH[8][2];
#pragma unroll
        for (int nb = 0; nb < 4; nb++) {
            uint32_t rh[4];
            ldsm4(rh, stg + (wn * 64 + 16 * nb + lrow) * 48 + lhalf);
            bH[2 * nb][0] = rh[0]; bH[2 * nb][1] = rh[2];
            bH[2 * nb + 1][0] = rh[1]; bH[2 * nb + 1][1] = rh[3];
        }
#pragma unroll
        for (int j = 0; j < 8; j++) {
            mma_f16(acc0[0][j], a0[0], bH[j]);
            mma_f16(acc0[1][j], a0[1], bH[j]);
        }
        // kstep 2c+1 B (second image in chunk)
#pragma unroll
        for (int nb = 0; nb < 4; nb++) {
            uint32_t rh[4];
            ldsm4(rh, stg + 12288 + (wn * 64 + 16 * nb + lrow) * 48 + lhalf);
            bH[2 * nb][0] = rh[0]; bH[2 * nb][1] = rh[2];
            bH[2 * nb + 1][0] = rh[1]; bH[2 * nb + 1][1] = rh[3];
        }
        if (lane == 0) mbar_arrive(emptyb + slot * 8);
        if (c + 1 < 11) {      // prefetch A kstep 2c+2
#pragma unroll
            for (int i = 0; i < 2; i++)
                ldsm4(a0[i], sb + X_OFF + (wm + 16 * i + lrow) * XSTR + (2 * c + 2) * 32 + lhalf);
        }
#pragma unroll
        for (int j = 0; j < 8; j++) {
            mma_f16(acc0[0][j], a1[0], bH[j]);
            mma_f16(acc0[1][j], a1[1], bH[j]);
        }
        produce(c + 2);
    }
    __syncthreads();    // X reads done; region dead

    // epilogue 0 -> C1 (aliases X)
    {
#pragma unroll
        for (int i = 0; i < 2; i++)
#pragma unroll
            for (int j = 0; j < 8; j++) {
                int col = wn * 64 + j * 8 + (lane & 3) * 2;
                int row = wm + 16 * i + (lane >> 2);
                float b0v = g_bf0[col], b1v = g_bf0[col + 1];
                *(uint32_t*)(smc + C1_OFF + row * 528 + col * 2) =
                    pack_h2(__float2half_rn(fmaxf(acc0[i][j][0] + b0v, 0.f)),
                            __float2half_rn(fmaxf(acc0[i][j][1] + b1v, 0.f)));
                *(uint32_t*)(smc + C1_OFF + (row + 8) * 528 + col * 2) =
                    pack_h2(__float2half_rn(fmaxf(acc0[i][j][2] + b0v, 0.f)),
                            __float2half_rn(fmaxf(acc0[i][j][3] + b1v, 0.f)));
            }
    }
    __syncthreads();    // C1 visible

    // ================= Layer 1: [64x256] -> 128, 8 chunks =================
    float acc1[2][4][4];
#pragma unroll
    for (int i = 0; i < 2; i++)
#pragma unroll
        for (int j = 0; j < 4; j++)
#pragma unroll
            for (int q = 0; q < 4; q++) acc1[i][j][q] = 0.f;

#pragma unroll
    for (int i = 0; i < 2; i++)
        ldsm4(a0[i], sb + C1_OFF + (wm + 16 * i + lrow) * 528 + lhalf);

    for (int c = 0; c < 8; c++) {
        const int cg = GC_L1 + c, slot = cg & 1, par = (cg >> 1) & 1;
#pragma unroll
        for (int i = 0; i < 2; i++)
            ldsm4(a1[i], sb + C1_OFF + (wm + 16 * i + lrow) * 528 + (2 * c + 1) * 32 + lhalf);
        MBAR_WAIT(fullb + slot * 8, par);
        uint32_t stg = sb + WSTG + (uint32_t)slot * WSSZ;
        uint32_t bH[4][2];
#pragma unroll
        for (int nb = 0; nb < 2; nb++) {
            uint32_t rh[4];
            ldsm4(rh, stg + (wn * 32 + 16 * nb + lrow) * 48 + lhalf);
            bH[2 * nb][0] = rh[0]; bH[2 * nb][1] = rh[2];
            bH[2 * nb + 1][0] = rh[1]; bH[2 * nb + 1][1] = rh[3];
        }
#pragma unroll
        for (int j = 0; j < 4; j++) {
            mma_f16(acc1[0][j], a0[0], bH[j]);
            mma_f16(acc1[1][j], a0[1], bH[j]);
        }
#pragma unroll
        for (int nb = 0; nb < 2; nb++) {
            uint32_t rh[4];
            ldsm4(rh, stg + 6144 + (wn * 32 + 16 * nb + lrow) * 48 + lhalf);
            bH[2 * nb][0] = rh[0]; bH[2 * nb][1] = rh[2];
            bH[2 * nb + 1][0] = rh[1]; bH[2 * nb + 1][1] = rh[3];
        }
        if (lane == 0) mbar_arrive(emptyb + slot * 8);
        if (c + 1 < 8) {
#pragma unroll
            for (int i = 0; i < 2; i++)
                ldsm4(a0[i], sb + C1_OFF + (wm + 16 * i + lrow) * 528 + (2 * c + 2) * 32 + lhalf);
        }
#pragma unroll
        for (int j = 0; j < 4; j++) {
            mma_f16(acc1[0][j], a1[0], bH[j]);
            mma_f16(acc1[1][j], a1[1], bH[j]);
        }
        produce(cg + 2);
    }
    __syncthreads();    // C1 reads done; region dead

    // epilogue 1 -> C2 (aliases C1)
    {
#pragma unroll
        for (int i = 0; i < 2; i++)
#pragma unroll
            for (int j = 0; j < 4; j++) {
                int col = wn * 32 + j * 8 + (lane & 3) * 2;
                int row = wm + 16 * i + (lane >> 2);
                float b0v = g_bf1[col], b1v = g_bf1[col + 1];
                *(uint32_t*)(smc + C2_OFF + row * 272 + col * 2) =
                    pack_h2(__float2half_rn(fmaxf(acc1[i][j][0] + b0v, 0.f)),
                            __float2half_rn(fmaxf(acc1[i][j][1] + b1v, 0.f)));
                *(uint32_t*)(smc + C2_OFF + (row + 8) * 272 + col * 2) =
                    pack_h2(__float2half_rn(fmaxf(acc1[i][j][2] + b0v, 0.f)),
                            __float2half_rn(fmaxf(acc1[i][j][3] + b1v, 0.f)));
            }
    }
    __syncthreads();    // C2 visible

    // ================= Layer 2: [64x128] -> 64, 4 chunks =================
    float acc2[2][2][4];
#pragma unroll
    for (int i = 0; i < 2; i++)
#pragma unroll
        for (int j = 0; j < 2; j++)
#pragma unroll
            for (int q = 0; q < 4; q++) acc2[i][j][q] = 0.f;

#pragma unroll
    for (int i = 0; i < 2; i++)
        ldsm4(a0[i], sb + C2_OFF + (wm + 16 * i + lrow) * 272 + lhalf);

    for (int c = 0; c < 4; c++) {
        const int cg = GC_L2 + c, slot = cg & 1, par = (cg >> 1) & 1;
#pragma unroll
        for (int i = 0; i < 2; i++)
            ldsm4(a1[i], sb + C2_OFF + (wm + 16 * i + lrow) * 272 + (2 * c + 1) * 32 + lhalf);
        MBAR_WAIT(fullb + slot * 8, par);
        uint32_t stg = sb + WSTG + (uint32_t)slot * WSSZ;
        uint32_t bH[2][2];
        {
            uint32_t rh[4];
            ldsm4(rh, stg + (wn * 16 + lrow) * 48 + lhalf);
            bH[0][0] = rh[0]; bH[0][1] = rh[2]; bH[1][0] = rh[1]; bH[1][1] = rh[3];
        }
#pragma unroll
        for (int j = 0; j < 2; j++) {
            mma_f16(acc2[0][j], a0[0], bH[j]);
            mma_f16(acc2[1][j], a0[1], bH[j]);
        }
        {
            uint32_t rh[4];
            ldsm4(rh, stg + 3072 + (wn * 16 + lrow) * 48 + lhalf);
            bH[0][0] = rh[0]; bH[0][1] = rh[2]; bH[1][0] = rh[1]; bH[1][1] = rh[3];
        }
        if (lane == 0) mbar_arrive(emptyb + slot * 8);
        if (c + 1 < 4) {
#pragma unroll
            for (int i = 0; i < 2; i++)
                ldsm4(a0[i], sb + C2_OFF + (wm + 16 * i + lrow) * 272 + (2 * c + 2) * 32 + lhalf);
        }
#pragma unroll
        for (int j = 0; j < 2; j++) {
            mma_f16(acc2[0][j], a1[0], bH[j]);
            mma_f16(acc2[1][j], a1[1], bH[j]);
        }
        if (cg + 2 < GC_END) produce(cg + 2);
    }

    // epilogue 2 -> C3 (f32, above C2 region)
    {
#pragma unroll
        for (int i = 0; i < 2; i++)
#pragma unroll
            for (int j = 0; j < 2; j++) {
                int col = wn * 16 + j * 8 + (lane & 3) * 2;
                int row = wm + 16 * i + (lane >> 2);
                float b0v = g_bf2[col], b1v = g_bf2[col + 1];
                float2 v01 = make_float2(fmaxf(acc2[i][j][0] + b0v, 0.f),
                                         fmaxf(acc2[i][j][1] + b1v, 0.f));
                float2 v23 = make_float2(fmaxf(acc2[i][j][2] + b0v, 0.f),
                                         fmaxf(acc2[i][j][3] + b1v, 0.f));
                *(float2*)(smc + C3F + row * 272 + col * 4) = v01;
                *(float2*)(smc + C3F + (row + 8) * 272 + col * 4) = v23;
            }
    }
    __syncthreads();

    // ================= Output: dot Wo + fm + sigmoid =================
    if (t < MTILE) {
        const float* c3 = (const float*)(smc + C3F) + t * 68;
        float s = *(const float*)(smc + FMS + t * 4) + fmb[0] + bo[0];
#pragma unroll
        for (int k = 0; k < N2; k++)
            s = fmaf(c3[k], __ldg(&Wo[k]), s);
        out[m0g + t] = 1.f / (1.f + __expf(-s));
    }
}

// ================= Launch =================
extern "C" void kernel_launch(void* const* d_in, const int* in_sizes, int n_in,
                              void* d_out, int out_size)
{
    const int*   sp    = (const int*)  d_in[0];
    const float* dense = (const float*)d_in[1];
    const float* emb   = (const float*)d_in[2];
    const float* bias  = (const float*)d_in[3];
    const float* fmb   = (const float*)d_in[4];
    const float* Wo    = (const float*)d_in[5];
    const float* bo    = (const float*)d_in[6];
    const float* W0    = (const float*)d_in[7];
    const float* b0    = (const float*)d_in[8];
    const float* g0    = (const float*)d_in[9];
    const float* be0   = (const float*)d_in[10];
    const float* W1    = (const float*)d_in[11];
    const float* b1    = (const float*)d_in[12];
    const float* g1    = (const float*)d_in[13];
    const float* be1   = (const float*)d_in[14];
    const float* W2    = (const float*)d_in[15];
    const float* b2    = (const float*)d_in[16];
    const float* g2    = (const float*)d_in[17];
    const float* be2   = (const float*)d_in[18];
    float* out = (float*)d_out;

    prep_all<<<PREP_TOT / 256, 256>>>(W0, b0, g0, be0, W1, b1, g1, be1, W2, b2, g2, be2);

    cudaFuncSetAttribute(mlp_kernel, cudaFuncAttributeMaxDynamicSharedMemorySize, SMEM_DYN);
    mlp_kernel<<<NCTA, NTHR, SMEM_DYN>>>(sp, dense, emb, bias, fmb, Wo, bo, out);
}